// round 6
// baseline (speedup 1.0000x reference)
#include <cuda_runtime.h>
#include <cstdint>

// ============================ constants ============================
constexpr int IN_F  = 4096;
constexpr int OUT_F = 4096;
constexpr int RANK  = 16;
constexpr int MROWS = 8192;             // B*T
constexpr float LSCALE = 2.0f;          // alpha/r = 32/16

constexpr int TM = 128;
constexpr int TN = 256;
constexpr int TK = 32;
constexpr int K_MAIN  = IN_F / TK;      // 128 main k-tiles
constexpr int NITER   = K_MAIN + 1;     // +1 LoRA ext tile (K=16 zero-padded)
constexpr int M_TILES = MROWS / TM;     // 64
constexpr int N_TILES = OUT_F / TN;     // 16

constexpr int PADK = 36;                // floats per smem row (32 + 4 pad)
constexpr int A_ROWS = TM;              // 128
constexpr int B_ROWS = TN;              // 256
constexpr int STAGE_FLOATS = (A_ROWS + B_ROWS) * PADK;   // 13824
constexpr int NSTAGE = 3;
constexpr int SM_BIAS_F = NSTAGE * STAGE_FLOATS;         // float offset of bias
constexpr int SMEM_BYTES = (SM_BIAS_F + TN) * 4 + 256;

// device scratch (static allocation is allowed)
__device__ float g_h [MROWS * RANK];            // scaled, tf32-rounded lora_h
__device__ float g_xc[(size_t)MROWS * IN_F];    // tf32-rounded x
__device__ float g_wc[(size_t)OUT_F * IN_F];    // tf32-rounded W

// ============================ helpers ============================
__device__ __forceinline__ uint32_t smem_u32(const void* p) {
    uint32_t a;
    asm("{ .reg .u64 t; cvta.to.shared.u64 t, %1; cvt.u32.u64 %0, t; }"
        : "=r"(a) : "l"(p));
    return a;
}

__device__ __forceinline__ float to_tf32(float x) {
    uint32_t u;
    asm("cvt.rna.tf32.f32 %0, %1;" : "=r"(u) : "f"(x));
    return __uint_as_float(u);
}

__device__ __forceinline__ void cp_async16(uint32_t dst_smem, const void* src) {
    asm volatile("cp.async.cg.shared.global [%0], [%1], 16;"
                 :: "r"(dst_smem), "l"(src) : "memory");
}
__device__ __forceinline__ void cp_commit() {
    asm volatile("cp.async.commit_group;" ::: "memory");
}
__device__ __forceinline__ void cp_wait2() {
    asm volatile("cp.async.wait_group 2;" ::: "memory");
}

__device__ __forceinline__ void mma_tf32(float* d, const uint32_t* a,
                                         const uint32_t* b) {
    asm volatile(
        "mma.sync.aligned.m16n8k8.row.col.f32.tf32.tf32.f32 "
        "{%0,%1,%2,%3}, {%4,%5,%6,%7}, {%8,%9}, {%0,%1,%2,%3};"
        : "+f"(d[0]), "+f"(d[1]), "+f"(d[2]), "+f"(d[3])
        : "r"(a[0]), "r"(a[1]), "r"(a[2]), "r"(a[3]),
          "r"(b[0]), "r"(b[1]));
}

// ============================ kernel 0: tf32 pre-convert ============================
constexpr size_t NX4 = (size_t)MROWS * IN_F / 4;    // 8388608
constexpr size_t NW4 = (size_t)OUT_F * IN_F / 4;    // 4194304

__global__ __launch_bounds__(256) void conv_kernel(const float4* __restrict__ x,
                                                   const float4* __restrict__ W) {
    size_t i = (size_t)blockIdx.x * 256 + threadIdx.x;
    size_t stride = (size_t)gridDim.x * 256;
    float4* gx = (float4*)g_xc;
    float4* gw = (float4*)g_wc;
    for (; i < NX4 + NW4; i += stride) {
        if (i < NX4) {
            float4 v = x[i];
            v.x = to_tf32(v.x); v.y = to_tf32(v.y);
            v.z = to_tf32(v.z); v.w = to_tf32(v.w);
            gx[i] = v;
        } else {
            size_t j = i - NX4;
            float4 v = W[j];
            v.x = to_tf32(v.x); v.y = to_tf32(v.y);
            v.z = to_tf32(v.z); v.w = to_tf32(v.w);
            gw[j] = v;
        }
    }
}

// ============================ kernel 1: lora_h ============================
// h[m, r] = tf32( LSCALE * sum_k x[m,k] * A[slot(m), k, r] )
__global__ __launch_bounds__(256) void lora_h_kernel(
    const float* __restrict__ x, const int* __restrict__ amap,
    const float* __restrict__ As)
{
    __shared__ float a_sm[512 * 20];
    const int row0 = blockIdx.x * 32;
    const int slot = amap[row0 >> 10];
    const float* A = As + (size_t)slot * (IN_F * RANK);
    const int w = threadIdx.x >> 5, lane = threadIdx.x & 31;
    const float* xr = x + (size_t)(row0 + 4 * w) * IN_F;

    float acc[4][16];
#pragma unroll
    for (int a = 0; a < 4; a++)
#pragma unroll
        for (int r = 0; r < 16; r++) acc[a][r] = 0.f;

    for (int k0 = 0; k0 < IN_F; k0 += 512) {
        __syncthreads();
        const float4* Ag = (const float4*)(A + (size_t)k0 * RANK);
        for (int i = threadIdx.x; i < 2048; i += 256) {
            int k = i >> 2, part = i & 3;
            *(float4*)(a_sm + k * 20 + part * 4) = Ag[i];
        }
        __syncthreads();
#pragma unroll 4
        for (int kk = lane; kk < 512; kk += 32) {
            const float4* a4 = (const float4*)(a_sm + kk * 20);
            float4 a0 = a4[0], a1 = a4[1], a2 = a4[2], a3 = a4[3];
#pragma unroll
            for (int rr = 0; rr < 4; rr++) {
                float xv = xr[(size_t)rr * IN_F + k0 + kk];
                acc[rr][0]  += xv * a0.x; acc[rr][1]  += xv * a0.y;
                acc[rr][2]  += xv * a0.z; acc[rr][3]  += xv * a0.w;
                acc[rr][4]  += xv * a1.x; acc[rr][5]  += xv * a1.y;
                acc[rr][6]  += xv * a1.z; acc[rr][7]  += xv * a1.w;
                acc[rr][8]  += xv * a2.x; acc[rr][9]  += xv * a2.y;
                acc[rr][10] += xv * a2.z; acc[rr][11] += xv * a2.w;
                acc[rr][12] += xv * a3.x; acc[rr][13] += xv * a3.y;
                acc[rr][14] += xv * a3.z; acc[rr][15] += xv * a3.w;
            }
        }
    }
#pragma unroll
    for (int off = 16; off > 0; off >>= 1)
#pragma unroll
        for (int rr = 0; rr < 4; rr++)
#pragma unroll
            for (int r = 0; r < 16; r++)
                acc[rr][r] += __shfl_xor_sync(0xffffffffu, acc[rr][r], off);

#pragma unroll
    for (int rr = 0; rr < 4; rr++) {
        float v = acc[rr][0];
#pragma unroll
        for (int r = 1; r < 16; r++)
            if (lane == r) v = acc[rr][r];
        if (lane < 16)
            g_h[(size_t)(row0 + 4 * w + rr) * RANK + lane] = to_tf32(v * LSCALE);
    }
}

// ============================ kernel 2: main fused GEMM ============================
__global__ __launch_bounds__(512, 1) void lora_main_kernel(
    const int* __restrict__ amap, const float* __restrict__ bias,
    const float* __restrict__ lBs, float* __restrict__ out)
{
    extern __shared__ float sm[];
    const uint32_t sm_base = smem_u32(sm);

    const int tid  = threadIdx.x;
    const int wid  = tid >> 5;
    const int lane = tid & 31;
    const int g  = lane >> 2;       // group id 0..7
    const int tg = lane & 3;        // thread in group 0..3
    const int warp_m = wid & 3;     // 0..3 -> 32-row slab
    const int warp_n = wid >> 2;    // 0..3 -> 64-col slab

    // block swizzle: 8 M-tiles x all 16 N-tiles per chunk keeps W in L2
    const int bid    = blockIdx.x;
    const int chunk  = bid >> 7;
    const int within = bid & 127;
    const int mt = (chunk << 3) + (within & 7);
    const int nt = within >> 3;
    const int m0 = mt * TM;
    const int n0 = nt * TN;
    const int slot = amap[m0 >> 10];

    // stage bias
    if (tid < TN / 4)
        *(float4*)(sm + SM_BIAS_F + tid * 4) =
            *(const float4*)(bias + n0 + tid * 4);

    const float* lB = lBs + (size_t)slot * RANK * OUT_F + n0;

    // ---------------- stage loader ----------------
    auto load_stage = [&](int it, int stage) {
        float* sA = sm + stage * STAGE_FLOATS;
        float* sB = sA + A_ROWS * PADK;
        const uint32_t sAu = sm_base + (uint32_t)(stage * STAGE_FLOATS) * 4;
        const uint32_t sBu = sAu + A_ROWS * PADK * 4;
        if (it < K_MAIN) {
            const int k0 = it * TK;
            const float* ga = g_xc + (size_t)m0 * IN_F + k0;
            const float* gb = g_wc + (size_t)n0 * IN_F + k0;
#pragma unroll
            for (int e = 0; e < 2; e++) {          // A: 128 rows x 8 chunks
                int idx = tid + e * 512;
                int r = idx >> 3, c = idx & 7;
                cp_async16(sAu + r * 144 + c * 16, ga + (size_t)r * IN_F + c * 4);
            }
#pragma unroll
            for (int e = 0; e < 4; e++) {          // B: 256 rows x 8 chunks
                int idx = tid + e * 512;
                int r = idx >> 3, c = idx & 7;
                cp_async16(sBu + r * 144 + c * 16, gb + (size_t)r * IN_F + c * 4);
            }
        } else {
            // ext LoRA tile: A = h[m][0..15] (cols 16..31 zero), B = lB^T
            const float4 z4 = make_float4(0.f, 0.f, 0.f, 0.f);
#pragma unroll
            for (int e = 0; e < 2; e++) {
                int idx = tid + e * 512;
                int r = idx >> 3, c = idx & 7;
                if (c < 4)
                    cp_async16(sAu + r * 144 + c * 16,
                               g_h + (size_t)(m0 + r) * RANK + c * 4);
                else
                    *(float4*)(sA + r * PADK + c * 4) = z4;
            }
#pragma unroll
            for (int e = 0; e < 8; e++) {          // B ext values (transposed)
                int idx = tid + e * 512;
                int rr = idx >> 8, n = idx & 255;
                sB[n * PADK + rr] = to_tf32(lB[(size_t)rr * OUT_F + n]);
            }
#pragma unroll
            for (int e = 0; e < 2; e++) {          // B ext zero pad cols 16..31
                int idx = tid + e * 512;
                int n = idx >> 2, q = idx & 3;
                *(float4*)(sB + n * PADK + 16 + q * 4) = z4;
            }
        }
    };

    // ---------------- accumulators ----------------
    float acc[2][8][4];
#pragma unroll
    for (int a = 0; a < 2; a++)
#pragma unroll
        for (int b = 0; b < 8; b++)
#pragma unroll
            for (int c = 0; c < 4; c++) acc[a][b][c] = 0.f;

    // prologue: prefetch 2 stages
    load_stage(0, 0); cp_commit();
    load_stage(1, 1); cp_commit();

    for (int it = 0; it < NITER; ++it) {
        const int stage = it % NSTAGE;
        if (it + 2 < NITER) load_stage(it + 2, (it + 2) % NSTAGE);
        cp_commit();                 // always commit (empty groups at tail)
        cp_wait2();
        __syncthreads();

        const float* sA = sm + stage * STAGE_FLOATS;
        const float* sB = sA + A_ROWS * PADK;
#pragma unroll
        for (int ks = 0; ks < 4; ks++) {
            const int kc = ks * 8 + tg;
            uint32_t af[2][4];
#pragma unroll
            for (int mt_ = 0; mt_ < 2; mt_++) {
                const int r0 = warp_m * 32 + mt_ * 16 + g;
                af[mt_][0] = __float_as_uint(sA[r0 * PADK + kc]);
                af[mt_][1] = __float_as_uint(sA[(r0 + 8) * PADK + kc]);
                af[mt_][2] = __float_as_uint(sA[r0 * PADK + kc + 4]);
                af[mt_][3] = __float_as_uint(sA[(r0 + 8) * PADK + kc + 4]);
            }
            uint32_t bf[8][2];
#pragma unroll
            for (int nt_ = 0; nt_ < 8; nt_++) {
                const int n = warp_n * 64 + nt_ * 8 + g;
                bf[nt_][0] = __float_as_uint(sB[n * PADK + kc]);
                bf[nt_][1] = __float_as_uint(sB[n * PADK + kc + 4]);
            }
#pragma unroll
            for (int mt_ = 0; mt_ < 2; mt_++)
#pragma unroll
                for (int nt_ = 0; nt_ < 8; nt_++)
                    mma_tf32(acc[mt_][nt_], af[mt_], bf[nt_]);
        }
        __syncthreads();
    }

    // ---------------- epilogue: bias + store ----------------
    const float* bsm = sm + SM_BIAS_F;
#pragma unroll
    for (int mt_ = 0; mt_ < 2; mt_++) {
        const int row = m0 + warp_m * 32 + mt_ * 16 + g;
        float* o0 = out + (size_t)row * OUT_F + n0;
        float* o1 = o0 + 8 * OUT_F;
#pragma unroll
        for (int nt_ = 0; nt_ < 8; nt_++) {
            const int col = warp_n * 64 + nt_ * 8 + 2 * tg;
            const float bx = bsm[col], by = bsm[col + 1];
            float2 v0 = make_float2(acc[mt_][nt_][0] + bx, acc[mt_][nt_][1] + by);
            float2 v1 = make_float2(acc[mt_][nt_][2] + bx, acc[mt_][nt_][3] + by);
            *(float2*)(o0 + col) = v0;
            *(float2*)(o1 + col) = v1;
        }
    }
}

// ============================ launch ============================
extern "C" void kernel_launch(void* const* d_in, const int* in_sizes, int n_in,
                              void* d_out, int out_size) {
    const float* x    = (const float*)d_in[0];
    const int*   amap = (const int*)d_in[1];
    const float* W    = (const float*)d_in[2];
    const float* bias = (const float*)d_in[3];
    const float* As   = (const float*)d_in[4];
    const float* Bs   = (const float*)d_in[5];
    float* out = (float*)d_out;

    cudaFuncSetAttribute(lora_main_kernel,
                         cudaFuncAttributeMaxDynamicSharedMemorySize, SMEM_BYTES);

    conv_kernel<<<4096, 256>>>((const float4*)x, (const float4*)W);
    lora_h_kernel<<<MROWS / 32, 256>>>(x, amap, As);
    lora_main_kernel<<<M_TILES * N_TILES, 512, SMEM_BYTES>>>(amap, bias, Bs, out);
}

// round 15
// speedup vs baseline: 1.0316x; 1.0316x over previous
#include <cuda_runtime.h>
#include <cstdint>

// ============================ constants ============================
constexpr int IN_F  = 4096;
constexpr int OUT_F = 4096;
constexpr int RANK  = 16;
constexpr int MROWS = 8192;             // B*T
constexpr float LSCALE = 2.0f;          // alpha/r = 32/16

constexpr int TM = 128;
constexpr int TN = 128;
constexpr int TK = 32;
constexpr int K_MAIN  = IN_F / TK;      // 128 main k-tiles
constexpr int NITER   = K_MAIN + 1;     // +1 LoRA ext tile (K=16 zero-padded)
constexpr int M_TILES = MROWS / TM;     // 64
constexpr int N_TILES = OUT_F / TN;     // 32

constexpr int PADK = 36;                // floats per smem row (32 + 4 pad)
constexpr int A_ROWS = TM;              // 128
constexpr int B_ROWS = TN;              // 128
constexpr int STAGE_FLOATS = (A_ROWS + B_ROWS) * PADK;   // 9216
constexpr int NSTAGE = 3;
constexpr int SM_BIAS_F = NSTAGE * STAGE_FLOATS;         // 27648
constexpr int SMEM_BYTES = (SM_BIAS_F + TN) * 4 + 256;   // ~111.4 KB -> 2 CTAs/SM

// device scratch (static allocation is allowed)
__device__ float g_h [MROWS * RANK];            // scaled, tf32-rounded lora_h
__device__ float g_xc[(size_t)MROWS * IN_F];    // tf32-rounded x
__device__ float g_wc[(size_t)OUT_F * IN_F];    // tf32-rounded W

// ============================ helpers ============================
__device__ __forceinline__ uint32_t smem_u32(const void* p) {
    uint32_t a;
    asm("{ .reg .u64 t; cvta.to.shared.u64 t, %1; cvt.u32.u64 %0, t; }"
        : "=r"(a) : "l"(p));
    return a;
}

__device__ __forceinline__ float to_tf32(float x) {
    uint32_t u;
    asm("cvt.rna.tf32.f32 %0, %1;" : "=r"(u) : "f"(x));
    return __uint_as_float(u);
}

__device__ __forceinline__ void cp_async16(uint32_t dst_smem, const void* src) {
    asm volatile("cp.async.cg.shared.global [%0], [%1], 16;"
                 :: "r"(dst_smem), "l"(src) : "memory");
}
__device__ __forceinline__ void cp_commit() {
    asm volatile("cp.async.commit_group;" ::: "memory");
}
__device__ __forceinline__ void cp_wait2() {
    asm volatile("cp.async.wait_group 2;" ::: "memory");
}

__device__ __forceinline__ void mma_tf32(float* d, const uint32_t* a,
                                         const uint32_t* b) {
    asm volatile(
        "mma.sync.aligned.m16n8k8.row.col.f32.tf32.tf32.f32 "
        "{%0,%1,%2,%3}, {%4,%5,%6,%7}, {%8,%9}, {%0,%1,%2,%3};"
        : "+f"(d[0]), "+f"(d[1]), "+f"(d[2]), "+f"(d[3])
        : "r"(a[0]), "r"(a[1]), "r"(a[2]), "r"(a[3]),
          "r"(b[0]), "r"(b[1]));
}

// ============================ kernel 0: tf32 pre-convert ============================
constexpr size_t NX4 = (size_t)MROWS * IN_F / 4;    // 8388608
constexpr size_t NW4 = (size_t)OUT_F * IN_F / 4;    // 4194304

__global__ __launch_bounds__(256) void conv_kernel(const float4* __restrict__ x,
                                                   const float4* __restrict__ W) {
    size_t i = (size_t)blockIdx.x * 256 + threadIdx.x;
    size_t stride = (size_t)gridDim.x * 256;
    float4* gx = (float4*)g_xc;
    float4* gw = (float4*)g_wc;
    for (; i < NX4 + NW4; i += stride) {
        if (i < NX4) {
            float4 v = x[i];
            v.x = to_tf32(v.x); v.y = to_tf32(v.y);
            v.z = to_tf32(v.z); v.w = to_tf32(v.w);
            gx[i] = v;
        } else {
            size_t j = i - NX4;
            float4 v = W[j];
            v.x = to_tf32(v.x); v.y = to_tf32(v.y);
            v.z = to_tf32(v.z); v.w = to_tf32(v.w);
            gw[j] = v;
        }
    }
}

// ============================ kernel 1: lora_h ============================
// h[m, r] = tf32( LSCALE * sum_k x[m,k] * A[slot(m), k, r] )
__global__ __launch_bounds__(256) void lora_h_kernel(
    const float* __restrict__ x, const int* __restrict__ amap,
    const float* __restrict__ As)
{
    __shared__ float a_sm[512 * 20];
    const int row0 = blockIdx.x * 32;
    const int slot = amap[row0 >> 10];
    const float* A = As + (size_t)slot * (IN_F * RANK);
    const int w = threadIdx.x >> 5, lane = threadIdx.x & 31;
    const float* xr = x + (size_t)(row0 + 4 * w) * IN_F;

    float acc[4][16];
#pragma unroll
    for (int a = 0; a < 4; a++)
#pragma unroll
        for (int r = 0; r < 16; r++) acc[a][r] = 0.f;

    for (int k0 = 0; k0 < IN_F; k0 += 512) {
        __syncthreads();
        const float4* Ag = (const float4*)(A + (size_t)k0 * RANK);
        for (int i = threadIdx.x; i < 2048; i += 256) {
            int k = i >> 2, part = i & 3;
            *(float4*)(a_sm + k * 20 + part * 4) = Ag[i];
        }
        __syncthreads();
#pragma unroll 4
        for (int kk = lane; kk < 512; kk += 32) {
            const float4* a4 = (const float4*)(a_sm + kk * 20);
            float4 a0 = a4[0], a1 = a4[1], a2 = a4[2], a3 = a4[3];
#pragma unroll
            for (int rr = 0; rr < 4; rr++) {
                float xv = xr[(size_t)rr * IN_F + k0 + kk];
                acc[rr][0]  += xv * a0.x; acc[rr][1]  += xv * a0.y;
                acc[rr][2]  += xv * a0.z; acc[rr][3]  += xv * a0.w;
                acc[rr][4]  += xv * a1.x; acc[rr][5]  += xv * a1.y;
                acc[rr][6]  += xv * a1.z; acc[rr][7]  += xv * a1.w;
                acc[rr][8]  += xv * a2.x; acc[rr][9]  += xv * a2.y;
                acc[rr][10] += xv * a2.z; acc[rr][11] += xv * a2.w;
                acc[rr][12] += xv * a3.x; acc[rr][13] += xv * a3.y;
                acc[rr][14] += xv * a3.z; acc[rr][15] += xv * a3.w;
            }
        }
    }
#pragma unroll
    for (int off = 16; off > 0; off >>= 1)
#pragma unroll
        for (int rr = 0; rr < 4; rr++)
#pragma unroll
            for (int r = 0; r < 16; r++)
                acc[rr][r] += __shfl_xor_sync(0xffffffffu, acc[rr][r], off);

#pragma unroll
    for (int rr = 0; rr < 4; rr++) {
        float v = acc[rr][0];
#pragma unroll
        for (int r = 1; r < 16; r++)
            if (lane == r) v = acc[rr][r];
        if (lane < 16)
            g_h[(size_t)(row0 + 4 * w + rr) * RANK + lane] = to_tf32(v * LSCALE);
    }
}

// ============================ kernel 2: main fused GEMM ============================
// 128x128 CTA tile, 256 threads (8 warps: 4 warp_m x 2 warp_n, 32x64 warp tile),
// 2 CTAs/SM for latency overlap.
__global__ __launch_bounds__(256, 2) void lora_main_kernel(
    const int* __restrict__ amap, const float* __restrict__ bias,
    const float* __restrict__ lBs, float* __restrict__ out)
{
    extern __shared__ float sm[];
    const uint32_t sm_base = smem_u32(sm);

    const int tid  = threadIdx.x;
    const int wid  = tid >> 5;
    const int lane = tid & 31;
    const int g  = lane >> 2;       // group id 0..7
    const int tg = lane & 3;        // thread in group 0..3
    const int warp_m = wid & 3;     // 0..3 -> 32-row slab
    const int warp_n = wid >> 2;    // 0..1 -> 64-col slab

    // block swizzle: 8 M-tiles x all 32 N-tiles per chunk keeps W in L2
    const int bid    = blockIdx.x;
    const int chunk  = bid >> 8;          // / (8*32)
    const int within = bid & 255;
    const int mt = (chunk << 3) + (within & 7);
    const int nt = within >> 3;
    const int m0 = mt * TM;
    const int n0 = nt * TN;
    const int slot = amap[m0 >> 10];

    // stage bias
    if (tid < TN / 4)
        *(float4*)(sm + SM_BIAS_F + tid * 4) =
            *(const float4*)(bias + n0 + tid * 4);

    const float* lB = lBs + (size_t)slot * RANK * OUT_F + n0;

    // ---------------- stage loader ----------------
    auto load_stage = [&](int it, int stage) {
        float* sA = sm + stage * STAGE_FLOATS;
        float* sB = sA + A_ROWS * PADK;
        const uint32_t sAu = sm_base + (uint32_t)(stage * STAGE_FLOATS) * 4;
        const uint32_t sBu = sAu + A_ROWS * PADK * 4;
        if (it < K_MAIN) {
            const int k0 = it * TK;
            const float* ga = g_xc + (size_t)m0 * IN_F + k0;
            const float* gb = g_wc + (size_t)n0 * IN_F + k0;
#pragma unroll
            for (int e = 0; e < 4; e++) {          // A: 128 rows x 8 chunks
                int idx = tid + e * 256;
                int r = idx >> 3, c = idx & 7;
                cp_async16(sAu + r * 144 + c * 16, ga + (size_t)r * IN_F + c * 4);
            }
#pragma unroll
            for (int e = 0; e < 4; e++) {          // B: 128 rows x 8 chunks
                int idx = tid + e * 256;
                int r = idx >> 3, c = idx & 7;
                cp_async16(sBu + r * 144 + c * 16, gb + (size_t)r * IN_F + c * 4);
            }
        } else {
            // ext LoRA tile: A = h[m][0..15] (cols 16..31 zero), B = lB^T
            const float4 z4 = make_float4(0.f, 0.f, 0.f, 0.f);
#pragma unroll
            for (int e = 0; e < 4; e++) {
                int idx = tid + e * 256;
                int r = idx >> 3, c = idx & 7;
                if (c < 4)
                    cp_async16(sAu + r * 144 + c * 16,
                               g_h + (size_t)(m0 + r) * RANK + c * 4);
                else
                    *(float4*)(sA + r * PADK + c * 4) = z4;
            }
#pragma unroll
            for (int e = 0; e < 8; e++) {          // B ext values (transposed) 16x128
                int idx = tid + e * 256;
                int rr = idx >> 7, n = idx & 127;
                sB[n * PADK + rr] = to_tf32(lB[(size_t)rr * OUT_F + n]);
            }
#pragma unroll
            for (int e = 0; e < 2; e++) {          // B ext zero pad cols 16..31
                int idx = tid + e * 256;
                int n = idx >> 2, q = idx & 3;
                *(float4*)(sB + n * PADK + 16 + q * 4) = z4;
            }
        }
    };

    // ---------------- accumulators ----------------
    float acc[2][8][4];
#pragma unroll
    for (int a = 0; a < 2; a++)
#pragma unroll
        for (int b = 0; b < 8; b++)
#pragma unroll
            for (int c = 0; c < 4; c++) acc[a][b][c] = 0.f;

    // prologue: prefetch 2 stages
    load_stage(0, 0); cp_commit();
    load_stage(1, 1); cp_commit();

    for (int it = 0; it < NITER; ++it) {
        const int stage = it % NSTAGE;
        if (it + 2 < NITER) load_stage(it + 2, (it + 2) % NSTAGE);
        cp_commit();                 // always commit (empty groups at tail)
        cp_wait2();
        __syncthreads();

        const float* sA = sm + stage * STAGE_FLOATS;
        const float* sB = sA + A_ROWS * PADK;
#pragma unroll
        for (int ks = 0; ks < 4; ks++) {
            const int kc = ks * 8 + tg;
            uint32_t af[2][4];
#pragma unroll
            for (int mt_ = 0; mt_ < 2; mt_++) {
                const int r0 = warp_m * 32 + mt_ * 16 + g;
                af[mt_][0] = __float_as_uint(sA[r0 * PADK + kc]);
                af[mt_][1] = __float_as_uint(sA[(r0 + 8) * PADK + kc]);
                af[mt_][2] = __float_as_uint(sA[r0 * PADK + kc + 4]);
                af[mt_][3] = __float_as_uint(sA[(r0 + 8) * PADK + kc + 4]);
            }
            // two nt-halves: keeps bf live range at 8 regs (no spills @128 cap)
#pragma unroll
            for (int half = 0; half < 2; half++) {
                uint32_t bf[4][2];
#pragma unroll
                for (int j = 0; j < 4; j++) {
                    const int n = warp_n * 64 + (half * 4 + j) * 8 + g;
                    bf[j][0] = __float_as_uint(sB[n * PADK + kc]);
                    bf[j][1] = __float_as_uint(sB[n * PADK + kc + 4]);
                }
#pragma unroll
                for (int mt_ = 0; mt_ < 2; mt_++)
#pragma unroll
                    for (int j = 0; j < 4; j++)
                        mma_tf32(acc[mt_][half * 4 + j], af[mt_], bf[j]);
            }
        }
        __syncthreads();
    }

    // ---------------- epilogue: bias + store ----------------
    const float* bsm = sm + SM_BIAS_F;
#pragma unroll
    for (int mt_ = 0; mt_ < 2; mt_++) {
        const int row = m0 + warp_m * 32 + mt_ * 16 + g;
        float* o0 = out + (size_t)row * OUT_F + n0;
        float* o1 = o0 + 8 * OUT_F;
#pragma unroll
        for (int nt_ = 0; nt_ < 8; nt_++) {
            const int col = warp_n * 64 + nt_ * 8 + 2 * tg;
            const float bx = bsm[col], by = bsm[col + 1];
            float2 v0 = make_float2(acc[mt_][nt_][0] + bx, acc[mt_][nt_][1] + by);
            float2 v1 = make_float2(acc[mt_][nt_][2] + bx, acc[mt_][nt_][3] + by);
            *(float2*)(o0 + col) = v0;
            *(float2*)(o1 + col) = v1;
        }
    }
}

// ============================ launch ============================
extern "C" void kernel_launch(void* const* d_in, const int* in_sizes, int n_in,
                              void* d_out, int out_size) {
    const float* x    = (const float*)d_in[0];
    const int*   amap = (const int*)d_in[1];
    const float* W    = (const float*)d_in[2];
    const float* bias = (const float*)d_in[3];
    const float* As   = (const float*)d_in[4];
    const float* Bs   = (const float*)d_in[5];
    float* out = (float*)d_out;

    cudaFuncSetAttribute(lora_main_kernel,
                         cudaFuncAttributeMaxDynamicSharedMemorySize, SMEM_BYTES);

    conv_kernel<<<4096, 256>>>((const float4*)x, (const float4*)W);
    lora_h_kernel<<<MROWS / 32, 256>>>(x, amap, As);
    lora_main_kernel<<<M_TILES * N_TILES, 256, SMEM_BYTES>>>(amap, bias, Bs, out);
}

// round 16
// speedup vs baseline: 1.6267x; 1.5769x over previous
#include <cuda_runtime.h>
#include <cuda_fp16.h>
#include <cstdint>

// ============================ constants ============================
constexpr int IN_F  = 4096;
constexpr int OUT_F = 4096;
constexpr int RANK  = 16;
constexpr int MROWS = 8192;             // B*T
constexpr float LSCALE = 2.0f;          // alpha/r = 32/16

constexpr int TM = 128;
constexpr int TN = 128;
constexpr int TK = 32;                  // halves per k-tile = 64B/row
constexpr int K_MAIN  = IN_F / TK;      // 128 main k-tiles
constexpr int NITER   = K_MAIN + 1;     // +1 LoRA ext tile (K=16 zero-padded)
constexpr int M_TILES = MROWS / TM;     // 64
constexpr int N_TILES = OUT_F / TN;     // 32

constexpr int ROW_B   = 80;             // bytes per smem row (64 data + 16 pad)
constexpr int STAGE_B = (TM + TN) * ROW_B;   // 20480 bytes
constexpr int NSTAGE  = 3;
constexpr int SM_BIAS_B = NSTAGE * STAGE_B;  // 61440
constexpr int SMEM_BYTES = SM_BIAS_B + TN * 4 + 128;  // ~62 KB -> 2 CTAs/SM

// device scratch (static allocation is allowed)
__device__ __half g_h [MROWS * RANK];            // scaled fp16 lora_h
__device__ __half g_xc[(size_t)MROWS * IN_F];    // fp16 x
__device__ __half g_wc[(size_t)OUT_F * IN_F];    // fp16 W

// ============================ helpers ============================
__device__ __forceinline__ uint32_t smem_u32(const void* p) {
    uint32_t a;
    asm("{ .reg .u64 t; cvta.to.shared.u64 t, %1; cvt.u32.u64 %0, t; }"
        : "=r"(a) : "l"(p));
    return a;
}

__device__ __forceinline__ void cp_async16(uint32_t dst_smem, const void* src) {
    asm volatile("cp.async.cg.shared.global [%0], [%1], 16;"
                 :: "r"(dst_smem), "l"(src) : "memory");
}
__device__ __forceinline__ void cp_commit() {
    asm volatile("cp.async.commit_group;" ::: "memory");
}
__device__ __forceinline__ void cp_wait2() {
    asm volatile("cp.async.wait_group 2;" ::: "memory");
}

__device__ __forceinline__ void mma_f16(float* d, const uint32_t* a,
                                        const uint32_t* b) {
    asm volatile(
        "mma.sync.aligned.m16n8k16.row.col.f32.f16.f16.f32 "
        "{%0,%1,%2,%3}, {%4,%5,%6,%7}, {%8,%9}, {%0,%1,%2,%3};"
        : "+f"(d[0]), "+f"(d[1]), "+f"(d[2]), "+f"(d[3])
        : "r"(a[0]), "r"(a[1]), "r"(a[2]), "r"(a[3]),
          "r"(b[0]), "r"(b[1]));
}

// ============================ kernel 0: fp16 pre-convert ============================
constexpr size_t NX4 = (size_t)MROWS * IN_F / 4;    // 8388608 float4s
constexpr size_t NW4 = (size_t)OUT_F * IN_F / 4;    // 4194304

__global__ __launch_bounds__(256) void conv_kernel(const float4* __restrict__ x,
                                                   const float4* __restrict__ W) {
    size_t i = (size_t)blockIdx.x * 256 + threadIdx.x;
    size_t stride = (size_t)gridDim.x * 256;
    uint2* gx = (uint2*)g_xc;
    uint2* gw = (uint2*)g_wc;
    for (; i < NX4 + NW4; i += stride) {
        if (i < NX4) {
            float4 v = x[i];
            __half2 h01 = __floats2half2_rn(v.x, v.y);
            __half2 h23 = __floats2half2_rn(v.z, v.w);
            uint2 u;
            u.x = *(uint32_t*)&h01;
            u.y = *(uint32_t*)&h23;
            gx[i] = u;
        } else {
            size_t j = i - NX4;
            float4 v = W[j];
            __half2 h01 = __floats2half2_rn(v.x, v.y);
            __half2 h23 = __floats2half2_rn(v.z, v.w);
            uint2 u;
            u.x = *(uint32_t*)&h01;
            u.y = *(uint32_t*)&h23;
            gw[j] = u;
        }
    }
}

// ============================ kernel 1: lora_h ============================
// h[m, r] = fp16( LSCALE * sum_k x[m,k] * A[slot(m), k, r] )
__global__ __launch_bounds__(256) void lora_h_kernel(
    const float* __restrict__ x, const int* __restrict__ amap,
    const float* __restrict__ As)
{
    __shared__ float a_sm[512 * 20];
    const int row0 = blockIdx.x * 32;
    const int slot = amap[row0 >> 10];
    const float* A = As + (size_t)slot * (IN_F * RANK);
    const int w = threadIdx.x >> 5, lane = threadIdx.x & 31;
    const float* xr = x + (size_t)(row0 + 4 * w) * IN_F;

    float acc[4][16];
#pragma unroll
    for (int a = 0; a < 4; a++)
#pragma unroll
        for (int r = 0; r < 16; r++) acc[a][r] = 0.f;

    for (int k0 = 0; k0 < IN_F; k0 += 512) {
        __syncthreads();
        const float4* Ag = (const float4*)(A + (size_t)k0 * RANK);
        for (int i = threadIdx.x; i < 2048; i += 256) {
            int k = i >> 2, part = i & 3;
            *(float4*)(a_sm + k * 20 + part * 4) = Ag[i];
        }
        __syncthreads();
#pragma unroll 4
        for (int kk = lane; kk < 512; kk += 32) {
            const float4* a4 = (const float4*)(a_sm + kk * 20);
            float4 a0 = a4[0], a1 = a4[1], a2 = a4[2], a3 = a4[3];
#pragma unroll
            for (int rr = 0; rr < 4; rr++) {
                float xv = xr[(size_t)rr * IN_F + k0 + kk];
                acc[rr][0]  += xv * a0.x; acc[rr][1]  += xv * a0.y;
                acc[rr][2]  += xv * a0.z; acc[rr][3]  += xv * a0.w;
                acc[rr][4]  += xv * a1.x; acc[rr][5]  += xv * a1.y;
                acc[rr][6]  += xv * a1.z; acc[rr][7]  += xv * a1.w;
                acc[rr][8]  += xv * a2.x; acc[rr][9]  += xv * a2.y;
                acc[rr][10] += xv * a2.z; acc[rr][11] += xv * a2.w;
                acc[rr][12] += xv * a3.x; acc[rr][13] += xv * a3.y;
                acc[rr][14] += xv * a3.z; acc[rr][15] += xv * a3.w;
            }
        }
    }
#pragma unroll
    for (int off = 16; off > 0; off >>= 1)
#pragma unroll
        for (int rr = 0; rr < 4; rr++)
#pragma unroll
            for (int r = 0; r < 16; r++)
                acc[rr][r] += __shfl_xor_sync(0xffffffffu, acc[rr][r], off);

#pragma unroll
    for (int rr = 0; rr < 4; rr++) {
        float v = acc[rr][0];
#pragma unroll
        for (int r = 1; r < 16; r++)
            if (lane == r) v = acc[rr][r];
        if (lane < 16)
            g_h[(size_t)(row0 + 4 * w + rr) * RANK + lane] =
                __float2half_rn(v * LSCALE);
    }
}

// ============================ kernel 2: main fused GEMM (fp16 m16n8k16) ============================
// 128x128 CTA tile, 256 threads (8 warps: 4 warp_m x 2 warp_n, 32x64 warp tile),
// 2 CTAs/SM. Same schedule as round-15 measured kernel; datapath fp16.
__global__ __launch_bounds__(256, 2) void lora_main_kernel(
    const int* __restrict__ amap, const float* __restrict__ bias,
    const float* __restrict__ lBs, float* __restrict__ out)
{
    extern __shared__ char smc[];
    const uint32_t sm_base = smem_u32(smc);

    const int tid  = threadIdx.x;
    const int wid  = tid >> 5;
    const int lane = tid & 31;
    const int g  = lane >> 2;       // group id 0..7
    const int tg = lane & 3;        // thread in group 0..3
    const int warp_m = wid & 3;     // 0..3 -> 32-row slab
    const int warp_n = wid >> 2;    // 0..1 -> 64-col slab

    // block swizzle: 8 M-tiles x all 32 N-tiles per chunk keeps W in L2
    const int bid    = blockIdx.x;
    const int chunk  = bid >> 8;          // / (8*32)
    const int within = bid & 255;
    const int mt = (chunk << 3) + (within & 7);
    const int nt = within >> 3;
    const int m0 = mt * TM;
    const int n0 = nt * TN;
    const int slot = amap[m0 >> 10];

    // stage bias (f32)
    float* bsm = (float*)(smc + SM_BIAS_B);
    if (tid < TN / 4)
        *(float4*)(bsm + tid * 4) = *(const float4*)(bias + n0 + tid * 4);

    const float* lB = lBs + (size_t)slot * RANK * OUT_F + n0;

    // ---------------- stage loader ----------------
    auto load_stage = [&](int it, int stage) {
        char* sA = smc + stage * STAGE_B;
        const uint32_t sAu = sm_base + (uint32_t)(stage * STAGE_B);
        const uint32_t sBu = sAu + TM * ROW_B;
        if (it < K_MAIN) {
            const int k0 = it * TK;
            const __half* ga = g_xc + (size_t)m0 * IN_F + k0;
            const __half* gb = g_wc + (size_t)n0 * IN_F + k0;
#pragma unroll
            for (int e = 0; e < 2; e++) {          // A: 128 rows x 4 chunks(16B)
                int idx = tid + e * 256;
                int r = idx >> 2, c = idx & 3;
                cp_async16(sAu + r * ROW_B + c * 16, ga + (size_t)r * IN_F + c * 8);
            }
#pragma unroll
            for (int e = 0; e < 2; e++) {          // B: 128 rows x 4 chunks
                int idx = tid + e * 256;
                int r = idx >> 2, c = idx & 3;
                cp_async16(sBu + r * ROW_B + c * 16, gb + (size_t)r * IN_F + c * 8);
            }
        } else {
            // ext LoRA tile: A = h[m][0..15] (halves 16..31 zero), B = lB^T fp16
            const float4 z4 = make_float4(0.f, 0.f, 0.f, 0.f);
#pragma unroll
            for (int e = 0; e < 2; e++) {
                int idx = tid + e * 256;
                int r = idx >> 2, c = idx & 3;
                if (c < 2)
                    cp_async16(sAu + r * ROW_B + c * 16,
                               g_h + (size_t)(m0 + r) * RANK + c * 8);
                else
                    *(float4*)(sA + r * ROW_B + c * 16) = z4;
            }
            __half* sBh = (__half*)(sA + TM * ROW_B);
#pragma unroll
            for (int e = 0; e < 8; e++) {          // B ext values (transposed) 16x128
                int idx = tid + e * 256;
                int rr = idx >> 7, n = idx & 127;
                sBh[n * (ROW_B / 2) + rr] =
                    __float2half_rn(lB[(size_t)rr * OUT_F + n]);
            }
            {                                      // B ext zero pad halves 16..31
                int n = tid >> 1, q = tid & 1;
                *(float4*)((char*)sBh + n * ROW_B + 32 + q * 16) = z4;
            }
        }
    };

    // ---------------- accumulators ----------------
    float acc[2][8][4];
#pragma unroll
    for (int a = 0; a < 2; a++)
#pragma unroll
        for (int b = 0; b < 8; b++)
#pragma unroll
            for (int c = 0; c < 4; c++) acc[a][b][c] = 0.f;

    // prologue: prefetch 2 stages
    load_stage(0, 0); cp_commit();
    load_stage(1, 1); cp_commit();

    for (int it = 0; it < NITER; ++it) {
        const int stage = it % NSTAGE;
        if (it + 2 < NITER) load_stage(it + 2, (it + 2) % NSTAGE);
        cp_commit();                 // always commit (empty groups at tail)
        cp_wait2();
        __syncthreads();

        const char* sA = smc + stage * STAGE_B;
        const char* sB = sA + TM * ROW_B;
#pragma unroll
        for (int ks = 0; ks < 2; ks++) {           // 2 x K=16 per 32-half tile
            const int kw = ks * 8 + tg;            // 32-bit word index in row
            uint32_t af[2][4];
#pragma unroll
            for (int mt_ = 0; mt_ < 2; mt_++) {
                const int r0 = warp_m * 32 + mt_ * 16 + g;
                af[mt_][0] = *(const uint32_t*)(sA + r0 * ROW_B + kw * 4);
                af[mt_][1] = *(const uint32_t*)(sA + (r0 + 8) * ROW_B + kw * 4);
                af[mt_][2] = *(const uint32_t*)(sA + r0 * ROW_B + (kw + 4) * 4);
                af[mt_][3] = *(const uint32_t*)(sA + (r0 + 8) * ROW_B + (kw + 4) * 4);
            }
#pragma unroll
            for (int half_ = 0; half_ < 2; half_++) {
                uint32_t bf[4][2];
#pragma unroll
                for (int j = 0; j < 4; j++) {
                    const int n = warp_n * 64 + (half_ * 4 + j) * 8 + g;
                    bf[j][0] = *(const uint32_t*)(sB + n * ROW_B + kw * 4);
                    bf[j][1] = *(const uint32_t*)(sB + n * ROW_B + (kw + 4) * 4);
                }
#pragma unroll
                for (int mt_ = 0; mt_ < 2; mt_++)
#pragma unroll
                    for (int j = 0; j < 4; j++)
                        mma_f16(acc[mt_][half_ * 4 + j], af[mt_], bf[j]);
            }
        }
        __syncthreads();
    }

    // ---------------- epilogue: bias + store ----------------
#pragma unroll
    for (int mt_ = 0; mt_ < 2; mt_++) {
        const int row = m0 + warp_m * 32 + mt_ * 16 + g;
        float* o0 = out + (size_t)row * OUT_F + n0;
        float* o1 = o0 + 8 * OUT_F;
#pragma unroll
        for (int nt_ = 0; nt_ < 8; nt_++) {
            const int col = warp_n * 64 + nt_ * 8 + 2 * tg;
            const float bx = bsm[col], by = bsm[col + 1];
            float2 v0 = make_float2(acc[mt_][nt_][0] + bx, acc[mt_][nt_][1] + by);
            float2 v1 = make_float2(acc[mt_][nt_][2] + bx, acc[mt_][nt_][3] + by);
            *(float2*)(o0 + col) = v0;
            *(float2*)(o1 + col) = v1;
        }
    }
}

// ============================ launch ============================
extern "C" void kernel_launch(void* const* d_in, const int* in_sizes, int n_in,
                              void* d_out, int out_size) {
    const float* x    = (const float*)d_in[0];
    const int*   amap = (const int*)d_in[1];
    const float* W    = (const float*)d_in[2];
    const float* bias = (const float*)d_in[3];
    const float* As   = (const float*)d_in[4];
    const float* Bs   = (const float*)d_in[5];
    float* out = (float*)d_out;

    cudaFuncSetAttribute(lora_main_kernel,
                         cudaFuncAttributeMaxDynamicSharedMemorySize, SMEM_BYTES);

    conv_kernel<<<4096, 256>>>((const float4*)x, (const float4*)W);
    lora_h_kernel<<<MROWS / 32, 256>>>(x, amap, As);
    lora_main_kernel<<<M_TILES * N_TILES, 256, SMEM_BYTES>>>(amap, bias, Bs, out);
}